// round 10
// baseline (speedup 1.0000x reference)
#include <cuda_runtime.h>
#include <cstdint>

#define D 128
#define WE 8        // edges per warp per pass
#define HALF 64     // columns per pass

__global__ __launch_bounds__(128, 12)
void tp_fused_kernel(const float* __restrict__ x,
                     const float* __restrict__ y,
                     const float* __restrict__ coeffs,
                     const void* __restrict__ srcp,
                     const void* __restrict__ dstp,
                     float* __restrict__ out,
                     int E, long long n_nodes, int warps_per_pass)
{
    // ---- index dtype detection, once per block (uniform, L2-hit broadcast)
    __shared__ int sh_i64;
    if (threadIdx.x == 0) {
        const long long* s64 = (const long long*)srcp;
        bool ok = true;
#pragma unroll
        for (int i = 0; i < 8; i++) {
            long long v = s64[i];
            if (v < 0 || v >= n_nodes) ok = false;
        }
        sh_i64 = ok ? 1 : 0;
    }
    __syncthreads();
    const bool i64 = (sh_i64 != 0);

    int gid   = blockIdx.x * blockDim.x + threadIdx.x;
    int gwarp = gid >> 5;
    // first half of grid = pass 0 (cols 0..63), second half = pass 1
    int pass  = (gwarp >= warps_per_pass) ? 1 : 0;
    int warp  = gwarp - pass * warps_per_pass;
    int lane  = gid & 31;
    int sub   = lane >> 4;                    // 16-lane sub-group
    int l16   = lane & 15;
    int col   = pass * HALF + (l16 << 2);     // 16B chunk in this pass's half-row
    int e0    = warp * WE;
    if (e0 >= E) return;
    int eb    = e0 + (sub << 2);              // this thread's 4 consecutive edges

    // ---- 1) y loads FIRST (longest latency, index-independent -> in flight early)
    float4 yv[4];
#pragma unroll
    for (int k = 0; k < 4; k++) {
        int e = eb + k;
        yv[k] = __ldcs(reinterpret_cast<const float4*>(
                     y + (size_t)min(e, E - 1) * D + col));
    }

    // ---- 2) vectorized index loads: 4 consecutive indices per wide LDG
    unsigned int s[4], d[4];
    if (e0 + WE <= E) {                       // full warp (uniform branch)
        if (i64) {
            const longlong2* sp = reinterpret_cast<const longlong2*>((const long long*)srcp + eb);
            const longlong2* dp = reinterpret_cast<const longlong2*>((const long long*)dstp + eb);
            longlong2 s01 = __ldg(sp), s23 = __ldg(sp + 1);
            longlong2 d01 = __ldg(dp), d23 = __ldg(dp + 1);
            s[0] = (unsigned int)s01.x; s[1] = (unsigned int)s01.y;
            s[2] = (unsigned int)s23.x; s[3] = (unsigned int)s23.y;
            d[0] = (unsigned int)d01.x; d[1] = (unsigned int)d01.y;
            d[2] = (unsigned int)d23.x; d[3] = (unsigned int)d23.y;
        } else {
            int4 sv = __ldg(reinterpret_cast<const int4*>((const int*)srcp + eb));
            int4 dv = __ldg(reinterpret_cast<const int4*>((const int*)dstp + eb));
            s[0] = (unsigned int)sv.x; s[1] = (unsigned int)sv.y;
            s[2] = (unsigned int)sv.z; s[3] = (unsigned int)sv.w;
            d[0] = (unsigned int)dv.x; d[1] = (unsigned int)dv.y;
            d[2] = (unsigned int)dv.z; d[3] = (unsigned int)dv.w;
        }
    } else {                                   // tail warp: scalar guarded
#pragma unroll
        for (int k = 0; k < 4; k++) {
            int e = eb + k;
            if (e < E) {
                if (i64) {
                    s[k] = (unsigned int)((const long long*)srcp)[e];
                    d[k] = (unsigned int)((const long long*)dstp)[e];
                } else {
                    s[k] = (unsigned int)((const int*)srcp)[e];
                    d[k] = (unsigned int)((const int*)dstp)[e];
                }
            } else { s[k] = 0; d[k] = 0; }
        }
    }

    // segment = col/32 ; per-pass base segment = pass*2
    float c = __ldg(coeffs + (pass << 1) + (l16 >> 3));

    // ---- 3) x gathers: 4 independent L2-hit chains
    float4 xv[4];
#pragma unroll
    for (int k = 0; k < 4; k++) {
        xv[k] = __ldg(reinterpret_cast<const float4*>(x + (size_t)s[k] * D + col));
    }

    // ---- 4) fused multiply + fire-and-forget vector reduction
#pragma unroll
    for (int k = 0; k < 4; k++) {
        if (eb + k < E) {
            float px = xv[k].x * yv[k].x * c;
            float py = xv[k].y * yv[k].y * c;
            float pz = xv[k].z * yv[k].z * c;
            float pw = xv[k].w * yv[k].w * c;
            float* addr = out + (size_t)d[k] * D + col;
            asm volatile("red.global.add.v4.f32 [%0], {%1, %2, %3, %4};"
                         :: "l"(addr), "f"(px), "f"(py), "f"(pz), "f"(pw)
                         : "memory");
        }
    }
}

extern "C" void kernel_launch(void* const* d_in, const int* in_sizes, int n_in,
                              void* d_out, int out_size) {
    const float* x      = (const float*)d_in[0];
    const float* y      = (const float*)d_in[1];
    const float* coeffs = (const float*)d_in[2];
    const void*  src    = d_in[3];
    const void*  dst    = d_in[4];
    float* out = (float*)d_out;

    int E = in_sizes[1] / D;
    long long n_nodes = (long long)(out_size / D);

    // zero the poisoned output via a graph-capturable memset node
    cudaMemsetAsync(d_out, 0, (size_t)out_size * sizeof(float), 0);

    int warps_per_pass = (E + WE - 1) / WE;            // 125k warps per pass
    long long total_threads = (long long)warps_per_pass * 2 * 32;
    int blocks = (int)((total_threads + 127) / 128);

    tp_fused_kernel<<<blocks, 128>>>(x, y, coeffs, src, dst, out,
                                     E, n_nodes, warps_per_pass);
}